// round 1
// baseline (speedup 1.0000x reference)
#include <cuda_runtime.h>
#include <cstdint>

// Problem constants
static constexpr int B_ = 32, T_ = 200, K_ = 50, D_ = 100;
static constexpr int NTILE = 8;                    // (b,t) tiles per CTA
static constexpr int NBLK  = (B_ * T_) / NTILE;    // 800
static constexpr int THREADS = 256;

// Shared layout (bytes). Strides chosen for conflict-free LDS.128/LDS.64:
// W_ht stride 204 floats -> 16B-chunk stride 51 (51 mod 8 = 3, coprime) -> CF
// W_rel stride 108 floats -> chunk stride 27 (27 mod 8 = 3)             -> CF
static constexpr int WHT_STRIDE  = 204;
static constexpr int WREL_STRIDE = 108;
static constexpr int OFF_WHT  = 0;
static constexpr int OFF_WREL = OFF_WHT  + 100 * WHT_STRIDE  * 4;   // 81600
static constexpr int OFF_HT   = OFF_WREL + 100 * WREL_STRIDE * 4;   // 124800
static constexpr int OFF_REL  = OFF_HT   + K_ * 200 * 4;            // 164800
static constexpr int OFF_BHT  = OFF_REL  + K_ * 100 * 4;            // 184800
static constexpr int OFF_BREL = OFF_BHT  + 112 * 4;                 // 185248
static constexpr int OFF_E    = OFF_BREL + 112 * 4;                 // 185696
static constexpr int SMEM_BYTES = OFF_E + 64 * 4;                   // 185952

// Packed f32x2 FMA (sm_103a): d = a*b + d elementwise on two fp32 lanes.
__device__ __forceinline__ void ffma2(unsigned long long& d,
                                      unsigned long long a,
                                      unsigned long long b) {
    asm("fma.rn.f32x2 %0, %1, %2, %3;" : "=l"(d) : "l"(a), "l"(b), "l"(d));
}

__device__ __forceinline__ float2 unpack2(unsigned long long v) {
    float2 r;
    asm("mov.b64 {%0, %1}, %2;" : "=f"(r.x), "=f"(r.y) : "l"(v));
    return r;
}

extern __shared__ __align__(16) unsigned char smem_raw[];

__global__ __launch_bounds__(THREADS, 1)
void outer_encoder_kernel(const unsigned int* __restrict__ idsw,  // raw 32-bit words of ids
                          const float* __restrict__ emb,
                          const float* __restrict__ Wht,
                          const float* __restrict__ bht,
                          const float* __restrict__ Wrel,
                          const float* __restrict__ brel,
                          float* __restrict__ out) {
    float* sWht  = (float*)(smem_raw + OFF_WHT);
    float* sWrel = (float*)(smem_raw + OFF_WREL);
    float* sHt   = (float*)(smem_raw + OFF_HT);    // [50][200] head|tail
    float* sRel  = (float*)(smem_raw + OFF_REL);   // [50][100]
    float* sbht  = (float*)(smem_raw + OFF_BHT);
    float* sbrel = (float*)(smem_raw + OFF_BREL);
    float* sE    = (float*)(smem_raw + OFF_E);     // e logits, then alpha

    const int tid  = threadIdx.x;
    const int w    = tid >> 5;
    const int lane = tid & 31;

    // ---- load weights once per CTA (float4 from gmem, padded-stride smem) ----
    {
        const float4* g = (const float4*)Wht;             // 5000 float4 (100x200)
        for (int i = tid; i < 5000; i += THREADS) {
            int d = i / 50, f4 = i % 50;
            *(float4*)(sWht + d * WHT_STRIDE + f4 * 4) = g[i];
        }
        const float4* gr = (const float4*)Wrel;           // 2500 float4 (100x100)
        for (int i = tid; i < 2500; i += THREADS) {
            int d = i / 25, f4 = i % 25;
            *(float4*)(sWrel + d * WREL_STRIDE + f4 * 4) = gr[i];
        }
        if (tid < 100) { sbht[tid] = bht[tid]; sbrel[tid] = brel[tid]; }
    }
    // Runtime int64-vs-int32 id detection: odd words all zero => int64.
    const int is64 = ((idsw[1] | idsw[3] | idsw[5] | idsw[7]) == 0) ? 1 : 0;
    __syncthreads();

    // Output-dim ownership: lane owns d = lane + 32*j, clamp (duplicate compute, discarded)
    int dc[4];
#pragma unroll
    for (int j = 0; j < 4; j++) { int d = lane + 32 * j; dc[j] = (d < D_) ? d : (D_ - 1); }
    // Triple ownership: warp owns k = 7w + i, clamp (duplicate compute, same value)
    int kc[7];
#pragma unroll
    for (int i = 0; i < 7; i++) { int k = w * 7 + i; kc[i] = (k < K_) ? k : (K_ - 1); }

    const float* wpH[4]; const float* wpR[4];
#pragma unroll
    for (int j = 0; j < 4; j++) {
        wpH[j] = sWht  + dc[j] * WHT_STRIDE;
        wpR[j] = sWrel + dc[j] * WREL_STRIDE;
    }

    const int tile0 = blockIdx.x * NTILE;

    for (int tt = 0; tt < NTILE; tt++) {
        const int tile = tile0 + tt;

        // ================= phase 1: gather all 50 triples into smem =================
        {
            const long long base = (long long)tile * (K_ * 3);
            for (int k = w; k < K_; k += 8) {
#pragma unroll
                for (int r = 0; r < 3; r++) {
                    long long e = base + k * 3 + r;
                    unsigned int id = is64 ? idsw[2 * e] : idsw[e];
                    const float2* src = (const float2*)(emb + (long long)id * D_);
                    float* dst = (r == 1) ? (sRel + k * 100)
                                          : (sHt + k * 200 + ((r == 2) ? 100 : 0));
                    float2* d2 = (float2*)dst;
                    for (int f = lane; f < 50; f += 32) d2[f] = __ldg(&src[f]);
                }
            }
        }
        __syncthreads();

        // ================= phase 2: per-warp e_weight for 7 triples =================
        {
            const float* xpR[7]; const float* xpH[7];
#pragma unroll
            for (int i = 0; i < 7; i++) {
                xpR[i] = sRel + kc[i] * 100;
                xpH[i] = sHt  + kc[i] * 200;
            }

            // ---- rel_t = W_rel @ rel + b_rel (kept in registers) ----
            unsigned long long racc[4][7];
#pragma unroll
            for (int j = 0; j < 4; j++)
#pragma unroll
                for (int i = 0; i < 7; i++) racc[j][i] = 0ull;

#pragma unroll 1
            for (int f = 0; f < 100; f += 4) {
                ulonglong2 wv[4];
#pragma unroll
                for (int j = 0; j < 4; j++)
                    wv[j] = *(const ulonglong2*)(wpR[j] + f);
#pragma unroll
                for (int i = 0; i < 7; i++) {
                    ulonglong2 xv = *(const ulonglong2*)(xpR[i] + f);
#pragma unroll
                    for (int j = 0; j < 4; j++) {
                        ffma2(racc[j][i], xv.x, wv[j].x);
                        ffma2(racc[j][i], xv.y, wv[j].y);
                    }
                }
            }
            float relt[4][7];
#pragma unroll
            for (int j = 0; j < 4; j++) {
                float bj = sbrel[dc[j]];
#pragma unroll
                for (int i = 0; i < 7; i++) {
                    float2 p = unpack2(racc[j][i]);
                    relt[j][i] = p.x + p.y + bj;
                }
            }

            // ---- ht_t = tanh(W_ht @ [head;tail] + b_ht), fused into e ----
            unsigned long long hacc[4][7];
#pragma unroll
            for (int j = 0; j < 4; j++)
#pragma unroll
                for (int i = 0; i < 7; i++) hacc[j][i] = 0ull;

#pragma unroll 1
            for (int f = 0; f < 200; f += 4) {
                ulonglong2 wv[4];
#pragma unroll
                for (int j = 0; j < 4; j++)
                    wv[j] = *(const ulonglong2*)(wpH[j] + f);
#pragma unroll
                for (int i = 0; i < 7; i++) {
                    ulonglong2 xv = *(const ulonglong2*)(xpH[i] + f);
#pragma unroll
                    for (int j = 0; j < 4; j++) {
                        ffma2(hacc[j][i], xv.x, wv[j].x);
                        ffma2(hacc[j][i], xv.y, wv[j].y);
                    }
                }
            }

            float e[7];
#pragma unroll
            for (int i = 0; i < 7; i++) e[i] = 0.f;
            float bj[4];
#pragma unroll
            for (int j = 0; j < 4; j++) bj[j] = sbht[dc[j]];
#pragma unroll
            for (int j = 0; j < 4; j++) {
                const bool valid = (lane + 32 * j) < D_;
#pragma unroll
                for (int i = 0; i < 7; i++) {
                    float2 p = unpack2(hacc[j][i]);
                    float h = tanhf(p.x + p.y + bj[j]);
                    if (valid) e[i] += relt[j][i] * h;
                }
            }
            // butterfly-reduce each e[i] across the warp; lane 0 publishes
#pragma unroll
            for (int i = 0; i < 7; i++) {
                float v = e[i];
#pragma unroll
                for (int off = 16; off > 0; off >>= 1)
                    v += __shfl_xor_sync(0xffffffffu, v, off);
                if (lane == 0) sE[kc[i]] = v;   // warp-7 clamp rewrites same value (benign)
            }
        }
        __syncthreads();

        // ================= softmax over K (warp 0) =================
        if (w == 0) {
            float v0 = (lane < K_)      ? sE[lane]      : -1e30f;
            float v1 = (lane + 32 < K_) ? sE[lane + 32] : -1e30f;
            float m = fmaxf(v0, v1);
#pragma unroll
            for (int off = 16; off > 0; off >>= 1)
                m = fmaxf(m, __shfl_xor_sync(0xffffffffu, m, off));
            float x0 = (lane < K_)      ? __expf(v0 - m) : 0.f;
            float x1 = (lane + 32 < K_) ? __expf(v1 - m) : 0.f;
            float s = x0 + x1;
#pragma unroll
            for (int off = 16; off > 0; off >>= 1)
                s += __shfl_xor_sync(0xffffffffu, s, off);
            float inv = 1.f / s;
            if (lane < K_)      sE[lane]      = x0 * inv;
            if (lane + 32 < K_) sE[lane + 32] = x1 * inv;
        }
        __syncthreads();

        // ================= weighted sum -> out[tile][0..199] =================
        if (tid < 200) {
            float acc = 0.f;
#pragma unroll
            for (int k = 0; k < K_; k++) acc += sE[k] * sHt[k * 200 + tid];
            out[(long long)tile * 200 + tid] = acc;
        }
        __syncthreads();
    }
}

extern "C" void kernel_launch(void* const* d_in, const int* in_sizes, int n_in,
                              void* d_out, int out_size) {
    const unsigned int* ids = nullptr;
    const float *emb = nullptr, *Wht = nullptr, *Wrel = nullptr;
    const float *bht = nullptr, *brel = nullptr;

    for (int i = 0; i < n_in; i++) {
        const int s = in_sizes[i];
        if      (s == B_ * T_ * K_ * 3) ids  = (const unsigned int*)d_in[i];   // 960000
        else if (s == 500000 * D_)      emb  = (const float*)d_in[i];          // 50M
        else if (s == D_ * 2 * D_)      Wht  = (const float*)d_in[i];          // 20000
        else if (s == D_ * D_)          Wrel = (const float*)d_in[i];          // 10000
        else if (s == D_) {                                                    // 100 (x2)
            if (!bht) bht = (const float*)d_in[i];
            else      brel = (const float*)d_in[i];
        }
    }

    cudaFuncSetAttribute(outer_encoder_kernel,
                         cudaFuncAttributeMaxDynamicSharedMemorySize, SMEM_BYTES);
    outer_encoder_kernel<<<NBLK, THREADS, SMEM_BYTES>>>(
        ids, emb, Wht, bht, Wrel, brel, (float*)d_out);
}

// round 2
// speedup vs baseline: 1.8466x; 1.8466x over previous
#include <cuda_runtime.h>
#include <cstdint>

// Problem constants
static constexpr int B_ = 32, T_ = 200, K_ = 50, D_ = 100;
static constexpr int NTILE = 8;                    // (b,t) tiles per CTA
static constexpr int NBLK  = (B_ * T_) / NTILE;    // 800
static constexpr int THREADS = 512;                // 16 warps -> 4 per SMSP

// Shared layout (bytes). Strides chosen for conflict-free LDS.128:
// W_ht stride 204 floats -> 16B-chunk stride 51 (mod 8 = 3, coprime) -> CF
// W_rel stride 108 floats -> chunk stride 27 (mod 8 = 3)             -> CF
static constexpr int WHT_STRIDE  = 204;
static constexpr int WREL_STRIDE = 108;
static constexpr int OFF_WHT  = 0;
static constexpr int OFF_WREL = OFF_WHT  + 100 * WHT_STRIDE  * 4;   // 81600
static constexpr int OFF_HT   = OFF_WREL + 100 * WREL_STRIDE * 4;   // 124800
static constexpr int OFF_REL  = OFF_HT   + K_ * 200 * 4;            // 164800
static constexpr int OFF_BHT  = OFF_REL  + K_ * 100 * 4;            // 184800
static constexpr int OFF_BREL = OFF_BHT  + 112 * 4;                 // 185248
static constexpr int OFF_E    = OFF_BREL + 112 * 4;                 // 185696
static constexpr int SMEM_BYTES = OFF_E + 2 * 56 * 4;               // 186144

// Packed f32x2 FMA (sm_103a): d = a*b + d elementwise on two fp32 lanes.
__device__ __forceinline__ void ffma2(unsigned long long& d,
                                      unsigned long long a,
                                      unsigned long long b) {
    asm("fma.rn.f32x2 %0, %1, %2, %3;" : "=l"(d) : "l"(a), "l"(b), "l"(d));
}

__device__ __forceinline__ float2 unpack2(unsigned long long v) {
    float2 r;
    asm("mov.b64 {%0, %1}, %2;" : "=f"(r.x), "=f"(r.y) : "l"(v));
    return r;
}

extern __shared__ __align__(16) unsigned char smem_raw[];

__global__ __launch_bounds__(THREADS, 1)
void outer_encoder_kernel(const unsigned int* __restrict__ idsw,  // raw 32-bit words of ids
                          const float* __restrict__ emb,
                          const float* __restrict__ Wht,
                          const float* __restrict__ bht,
                          const float* __restrict__ Wrel,
                          const float* __restrict__ brel,
                          float* __restrict__ out) {
    float* sWht  = (float*)(smem_raw + OFF_WHT);
    float* sWrel = (float*)(smem_raw + OFF_WREL);
    float* sHt   = (float*)(smem_raw + OFF_HT);    // [50][200] head|tail
    float* sRel  = (float*)(smem_raw + OFF_REL);   // [50][100]
    float* sbht  = (float*)(smem_raw + OFF_BHT);
    float* sbrel = (float*)(smem_raw + OFF_BREL);
    float* sEp   = (float*)(smem_raw + OFF_E);     // [2][56] partial e; then alpha in [0][0..49]

    const int tid  = threadIdx.x;
    const int w    = tid >> 5;
    const int lane = tid & 31;
    const int kgroup = w & 7;     // which 7 triples
    const int dhalf  = w >> 3;    // which pair of output-dim registers

    // ---- load weights once per CTA (float4 from gmem, padded-stride smem) ----
    {
        const float4* g = (const float4*)Wht;             // 5000 float4 (100x200)
        for (int i = tid; i < 5000; i += THREADS) {
            int d = i / 50, f4 = i % 50;
            *(float4*)(sWht + d * WHT_STRIDE + f4 * 4) = g[i];
        }
        const float4* gr = (const float4*)Wrel;           // 2500 float4 (100x100)
        for (int i = tid; i < 2500; i += THREADS) {
            int d = i / 25, f4 = i % 25;
            *(float4*)(sWrel + d * WREL_STRIDE + f4 * 4) = gr[i];
        }
        if (tid < 100) { sbht[tid] = bht[tid]; sbrel[tid] = brel[tid]; }
    }
    // Runtime int64-vs-int32 id detection: odd words all zero => int64.
    const int is64 = ((idsw[1] | idsw[3] | idsw[5] | idsw[7]) == 0) ? 1 : 0;
    __syncthreads();

    // Output-dim ownership: this warp's lane owns d = lane + 32*(2*dhalf + jj), jj in {0,1}
    int  dc[2];
    bool dvalid[2];
#pragma unroll
    for (int jj = 0; jj < 2; jj++) {
        int d = lane + 32 * (2 * dhalf + jj);
        dvalid[jj] = (d < D_);
        dc[jj] = dvalid[jj] ? d : (D_ - 1);
    }
    // Triple ownership: kgroup owns k = 7*kgroup + i (clamped duplicates write same value)
    int kc[7];
#pragma unroll
    for (int i = 0; i < 7; i++) { int k = kgroup * 7 + i; kc[i] = (k < K_) ? k : (K_ - 1); }

    const float* wpH[2]; const float* wpR[2];
#pragma unroll
    for (int jj = 0; jj < 2; jj++) {
        wpH[jj] = sWht  + dc[jj] * WHT_STRIDE;
        wpR[jj] = sWrel + dc[jj] * WREL_STRIDE;
    }

    const int tile0 = blockIdx.x * NTILE;

    for (int tt = 0; tt < NTILE; tt++) {
        const int tile = tile0 + tt;

        // ================= phase 1: gather all 150 rows into smem (float4) =============
        {
            const long long base = (long long)tile * (K_ * 3);
            for (int r = w; r < 150; r += 16) {
                const int k = r / 3, part = r % 3;
                long long e = base + r;
                unsigned int id = is64 ? idsw[2 * e] : idsw[e];
                const float4* src = (const float4*)(emb + (long long)id * D_);
                float* dst = (part == 1) ? (sRel + k * 100)
                                         : (sHt + k * 200 + ((part == 2) ? 100 : 0));
                if (lane < 25) ((float4*)dst)[lane] = __ldg(&src[lane]);
            }
        }
        __syncthreads();

        // ================= phase 2: per-warp e_weight partials =================
        {
            const float* xpR[7]; const float* xpH[7];
#pragma unroll
            for (int i = 0; i < 7; i++) {
                xpR[i] = sRel + kc[i] * 100;
                xpH[i] = sHt  + kc[i] * 200;
            }

            // ---- rel_t = W_rel @ rel + b_rel (registers) ----
            unsigned long long racc[2][7];
#pragma unroll
            for (int jj = 0; jj < 2; jj++)
#pragma unroll
                for (int i = 0; i < 7; i++) racc[jj][i] = 0ull;

#pragma unroll 5
            for (int f = 0; f < 100; f += 4) {
                ulonglong2 wv[2];
#pragma unroll
                for (int jj = 0; jj < 2; jj++)
                    wv[jj] = *(const ulonglong2*)(wpR[jj] + f);
#pragma unroll
                for (int i = 0; i < 7; i++) {
                    ulonglong2 xv = *(const ulonglong2*)(xpR[i] + f);
#pragma unroll
                    for (int jj = 0; jj < 2; jj++) {
                        ffma2(racc[jj][i], xv.x, wv[jj].x);
                        ffma2(racc[jj][i], xv.y, wv[jj].y);
                    }
                }
            }
            float relt[2][7];
#pragma unroll
            for (int jj = 0; jj < 2; jj++) {
                float bj = sbrel[dc[jj]];
#pragma unroll
                for (int i = 0; i < 7; i++) {
                    float2 p = unpack2(racc[jj][i]);
                    relt[jj][i] = p.x + p.y + bj;
                }
            }

            // ---- ht_t = tanh(W_ht @ [head;tail] + b_ht), fused into e ----
            unsigned long long hacc[2][7];
#pragma unroll
            for (int jj = 0; jj < 2; jj++)
#pragma unroll
                for (int i = 0; i < 7; i++) hacc[jj][i] = 0ull;

#pragma unroll 5
            for (int f = 0; f < 200; f += 4) {
                ulonglong2 wv[2];
#pragma unroll
                for (int jj = 0; jj < 2; jj++)
                    wv[jj] = *(const ulonglong2*)(wpH[jj] + f);
#pragma unroll
                for (int i = 0; i < 7; i++) {
                    ulonglong2 xv = *(const ulonglong2*)(xpH[i] + f);
#pragma unroll
                    for (int jj = 0; jj < 2; jj++) {
                        ffma2(hacc[jj][i], xv.x, wv[jj].x);
                        ffma2(hacc[jj][i], xv.y, wv[jj].y);
                    }
                }
            }

            float e[7];
#pragma unroll
            for (int i = 0; i < 7; i++) e[i] = 0.f;
#pragma unroll
            for (int jj = 0; jj < 2; jj++) {
                const float bj = sbht[dc[jj]];
#pragma unroll
                for (int i = 0; i < 7; i++) {
                    float2 p = unpack2(hacc[jj][i]);
                    float h = tanhf(p.x + p.y + bj);
                    if (dvalid[jj]) e[i] += relt[jj][i] * h;
                }
            }
            // butterfly-reduce each e[i] across the warp; lane 0 publishes partial
#pragma unroll
            for (int i = 0; i < 7; i++) {
                float v = e[i];
#pragma unroll
                for (int off = 16; off > 0; off >>= 1)
                    v += __shfl_xor_sync(0xffffffffu, v, off);
                if (lane == 0) sEp[dhalf * 56 + kc[i]] = v;   // clamp dups rewrite same value
            }
        }
        __syncthreads();

        // ================= softmax over K (warp 0), combining dim-halves =================
        if (w == 0) {
            float v0 = (lane < K_)      ? (sEp[lane]      + sEp[56 + lane])      : -1e30f;
            float v1 = (lane + 32 < K_) ? (sEp[lane + 32] + sEp[56 + lane + 32]) : -1e30f;
            float m = fmaxf(v0, v1);
#pragma unroll
            for (int off = 16; off > 0; off >>= 1)
                m = fmaxf(m, __shfl_xor_sync(0xffffffffu, m, off));
            float x0 = (lane < K_)      ? __expf(v0 - m) : 0.f;
            float x1 = (lane + 32 < K_) ? __expf(v1 - m) : 0.f;
            float s = x0 + x1;
#pragma unroll
            for (int off = 16; off > 0; off >>= 1)
                s += __shfl_xor_sync(0xffffffffu, s, off);
            float inv = 1.f / s;
            if (lane < K_)      sEp[lane]      = x0 * inv;
            if (lane + 32 < K_) sEp[lane + 32] = x1 * inv;
        }
        __syncthreads();

        // ================= weighted sum -> out[tile][0..199] =================
        if (tid < 200) {
            float acc = 0.f;
#pragma unroll
            for (int k = 0; k < K_; k++) acc += sEp[k] * sHt[k * 200 + tid];
            out[(long long)tile * 200 + tid] = acc;
        }
        __syncthreads();
    }
}

extern "C" void kernel_launch(void* const* d_in, const int* in_sizes, int n_in,
                              void* d_out, int out_size) {
    const unsigned int* ids = nullptr;
    const float *emb = nullptr, *Wht = nullptr, *Wrel = nullptr;
    const float *bht = nullptr, *brel = nullptr;

    for (int i = 0; i < n_in; i++) {
        const int s = in_sizes[i];
        if      (s == B_ * T_ * K_ * 3) ids  = (const unsigned int*)d_in[i];   // 960000
        else if (s == 500000 * D_)      emb  = (const float*)d_in[i];          // 50M
        else if (s == D_ * 2 * D_)      Wht  = (const float*)d_in[i];          // 20000
        else if (s == D_ * D_)          Wrel = (const float*)d_in[i];          // 10000
        else if (s == D_) {                                                    // 100 (x2)
            if (!bht) bht = (const float*)d_in[i];
            else      brel = (const float*)d_in[i];
        }
    }

    cudaFuncSetAttribute(outer_encoder_kernel,
                         cudaFuncAttributeMaxDynamicSharedMemorySize, SMEM_BYTES);
    outer_encoder_kernel<<<NBLK, THREADS, SMEM_BYTES>>>(
        ids, emb, Wht, bht, Wrel, brel, (float*)d_out);
}

// round 4
// speedup vs baseline: 3.3388x; 1.8080x over previous
#include <cuda_runtime.h>
#include <cuda_fp16.h>
#include <cstdint>

// Problem constants
static constexpr int B_ = 32, T_ = 200, K_ = 50, D_ = 100;
static constexpr int THREADS = 256;   // 8 warps
static constexpr int NTILE = 8;
static constexpr int NBLK  = 800;     // 800 x 8 = 6400 (b,t) tiles

// smem strides in halfs. Word-stride mod 32: 108%32=12, 60%32=28 -> both give
// all-32-distinct banks for the 8-row x 4-word fragment access pattern.
static constexpr int SWH = 216;   // Wht  [112 rows(d) x 216(k, 200 data + pad0)]
static constexpr int SWR = 120;   // Wrel [112 x 120 (100 data + pad0)]
static constexpr int SXH = 216;   // X    [64 rows(k-triples) x 216]
static constexpr int SRH = 120;   // REL  [64 x 120]

static constexpr int OFF_WHT  = 0;                 // 112*216*2 = 48384
static constexpr int OFF_WREL = 48384;             // 112*120*2 = 26880
static constexpr int OFF_X    = 75264;             // 64*216*2  = 27648
static constexpr int OFF_REL  = 102912;            // 64*120*2  = 15360
static constexpr int OFF_XF   = 118272;            // fp32 X copy 64*200*4 = 51200
static constexpr int OFF_BHT  = 169472;            // float[112]
static constexpr int OFF_BREL = 169920;            // float[112]
static constexpr int OFF_EP   = 170368;            // float[2][64]
static constexpr int OFF_AL   = 170880;            // float[64]
static constexpr int SMEM_BYTES = 171136;
static constexpr int ZERO_BYTES = OFF_XF;          // all fp16 tile buffers

__device__ __forceinline__ void mma16816(float& c0, float& c1, float& c2, float& c3,
                                         uint32_t a0, uint32_t a1, uint32_t a2, uint32_t a3,
                                         uint32_t b0, uint32_t b1) {
    asm volatile("mma.sync.aligned.m16n8k16.row.col.f32.f16.f16.f32 "
                 "{%0,%1,%2,%3}, {%4,%5,%6,%7}, {%8,%9}, {%0,%1,%2,%3};"
                 : "+f"(c0), "+f"(c1), "+f"(c2), "+f"(c3)
                 : "r"(a0), "r"(a1), "r"(a2), "r"(a3), "r"(b0), "r"(b1));
}

__device__ __forceinline__ uint32_t f2h2(float a, float b) {
    __half2 h = __floats2half2_rn(a, b);
    return *reinterpret_cast<uint32_t*>(&h);
}
__device__ __forceinline__ float tanh_fast(float x) {
    float e = __expf(2.f * x);
    return __fdividef(e - 1.f, e + 1.f);
}

extern __shared__ __align__(16) unsigned char smem_raw[];

__global__ __launch_bounds__(THREADS, 1)
void outer_encoder_mma(const unsigned int* __restrict__ idsw,
                       const float* __restrict__ emb,
                       const float* __restrict__ Wht,
                       const float* __restrict__ bht,
                       const float* __restrict__ Wrel,
                       const float* __restrict__ brel,
                       float* __restrict__ out) {
    unsigned char* sm = smem_raw;
    const int tid = threadIdx.x, w = tid >> 5, lane = tid & 31;
    const int gid = lane >> 2, tig = lane & 3;

    __half* sX   = (__half*)(sm + OFF_X);
    __half* sRl  = (__half*)(sm + OFF_REL);
    float*  sXf  = (float*)(sm + OFF_XF);
    float*  sbht = (float*)(sm + OFF_BHT);
    float*  sbrl = (float*)(sm + OFF_BREL);
    float*  sEp  = (float*)(sm + OFF_EP);
    float*  sAl  = (float*)(sm + OFF_AL);

    // ---- zero all fp16 tile buffers (pad rows/cols must stay 0) ----
    for (int i = tid; i < ZERO_BYTES / 16; i += THREADS)
        ((uint4*)sm)[i] = make_uint4(0, 0, 0, 0);
    __syncthreads();

    // ---- weights -> fp16 smem (data cols only; pads already 0) ----
    {
        const float4* g = (const float4*)Wht;              // [100][200] -> 5000 f4
        for (int i = tid; i < 5000; i += THREADS) {
            int d = i / 50, c4 = i % 50;
            float4 v = __ldg(&g[i]);
            uint2 hv; hv.x = f2h2(v.x, v.y); hv.y = f2h2(v.z, v.w);
            *(uint2*)(sm + OFF_WHT + (d * SWH + c4 * 4) * 2) = hv;
        }
        const float4* gr = (const float4*)Wrel;            // [100][100] -> 2500 f4
        for (int i = tid; i < 2500; i += THREADS) {
            int d = i / 25, c4 = i % 25;
            float4 v = __ldg(&gr[i]);
            uint2 hv; hv.x = f2h2(v.x, v.y); hv.y = f2h2(v.z, v.w);
            *(uint2*)(sm + OFF_WREL + (d * SWR + c4 * 4) * 2) = hv;
        }
        if (tid < 112) {
            sbht[tid] = (tid < D_) ? bht[tid]  : 0.f;
            sbrl[tid] = (tid < D_) ? brel[tid] : 0.f;
        }
    }
    const int is64 = ((idsw[1] | idsw[3] | idsw[5] | idsw[7]) == 0) ? 1 : 0;
    __syncthreads();

    const int mt = w & 3, nh = w >> 2;
    const int arow = mt * 16 + gid;

    for (int tt = 0; tt < NTILE; tt++) {
        const int tile = blockIdx.x * NTILE + tt;
        const long long ebase = (long long)tile * (K_ * 3);

        // ================= gather =================
        // X = [head|tail]: 100 tasks (k,half); also fp32 copy for the output sum.
        for (int task = w; task < 100; task += 8) {
            const int k = task >> 1, h = task & 1;
            const long long e = ebase + k * 3 + (h ? 2 : 0);
            const unsigned int id = is64 ? idsw[2 * e] : idsw[e];
            if (lane < 25) {
                float4 v = __ldg(&((const float4*)emb)[(long long)id * 25 + lane]);
                uint2 hv; hv.x = f2h2(v.x, v.y); hv.y = f2h2(v.z, v.w);
                *(uint2*)(sX + k * SXH + h * 100 + lane * 4) = hv;
                *(float4*)(sXf + k * 200 + h * 100 + lane * 4) = v;
            }
        }
        // REL: 50 tasks
        for (int task = w; task < 50; task += 8) {
            const long long e = ebase + task * 3 + 1;
            const unsigned int id = is64 ? idsw[2 * e] : idsw[e];
            if (lane < 25) {
                float4 v = __ldg(&((const float4*)emb)[(long long)id * 25 + lane]);
                uint2 hv; hv.x = f2h2(v.x, v.y); hv.y = f2h2(v.z, v.w);
                *(uint2*)(sRl + task * SRH + lane * 4) = hv;
            }
        }
        __syncthreads();

        // ================= dual GEMM on tensor cores =================
        float acc1[7][4], acc2[7][4];
#pragma unroll
        for (int nt = 0; nt < 7; nt++)
#pragma unroll
            for (int j = 0; j < 4; j++) { acc1[nt][j] = 0.f; acc2[nt][j] = 0.f; }

        {   // GEMM1: D1 = X[64x208] @ Wht[112x208]^T
            const __half* pX = sX;
            const __half* pW = (const __half*)(sm + OFF_WHT);
#pragma unroll
            for (int ks = 0; ks < 13; ks++) {
                const int k0 = ks * 16 + tig * 2;
                uint32_t a0 = *(const uint32_t*)(pX + arow * SXH + k0);
                uint32_t a1 = *(const uint32_t*)(pX + (arow + 8) * SXH + k0);
                uint32_t a2 = *(const uint32_t*)(pX + arow * SXH + k0 + 8);
                uint32_t a3 = *(const uint32_t*)(pX + (arow + 8) * SXH + k0 + 8);
#pragma unroll
                for (int nt = 0; nt < 7; nt++) {
                    const int brow = nh * 56 + nt * 8 + gid;
                    uint32_t b0 = *(const uint32_t*)(pW + brow * SWH + k0);
                    uint32_t b1 = *(const uint32_t*)(pW + brow * SWH + k0 + 8);
                    mma16816(acc1[nt][0], acc1[nt][1], acc1[nt][2], acc1[nt][3],
                             a0, a1, a2, a3, b0, b1);
                }
            }
        }
        {   // GEMM2: D2 = REL[64x112] @ Wrel[112x112]^T
            const __half* pR = sRl;
            const __half* pW = (const __half*)(sm + OFF_WREL);
#pragma unroll
            for (int ks = 0; ks < 7; ks++) {
                const int k0 = ks * 16 + tig * 2;
                uint32_t a0 = *(const uint32_t*)(pR + arow * SRH + k0);
                uint32_t a1 = *(const uint32_t*)(pR + (arow + 8) * SRH + k0);
                uint32_t a2 = *(const uint32_t*)(pR + arow * SRH + k0 + 8);
                uint32_t a3 = *(const uint32_t*)(pR + (arow + 8) * SRH + k0 + 8);
#pragma unroll
                for (int nt = 0; nt < 7; nt++) {
                    const int brow = nh * 56 + nt * 8 + gid;
                    uint32_t b0 = *(const uint32_t*)(pW + brow * SWR + k0);
                    uint32_t b1 = *(const uint32_t*)(pW + brow * SWR + k0 + 8);
                    mma16816(acc2[nt][0], acc2[nt][1], acc2[nt][2], acc2[nt][3],
                             a0, a1, a2, a3, b0, b1);
                }
            }
        }

        // ---- fused epilogue: e partials (padded cols: W=0,b=0 -> tanh(0)*0 = 0) ----
        {
            float e0 = 0.f, e1 = 0.f;
#pragma unroll
            for (int nt = 0; nt < 7; nt++) {
                const int c0 = nh * 56 + nt * 8 + tig * 2;
                const float bh0 = sbht[c0], bh1 = sbht[c0 + 1];
                const float br0 = sbrl[c0], br1 = sbrl[c0 + 1];
                e0 += tanh_fast(acc1[nt][0] + bh0) * (acc2[nt][0] + br0)
                    + tanh_fast(acc1[nt][1] + bh1) * (acc2[nt][1] + br1);
                e1 += tanh_fast(acc1[nt][2] + bh0) * (acc2[nt][2] + br0)
                    + tanh_fast(acc1[nt][3] + bh1) * (acc2[nt][3] + br1);
            }
            e0 += __shfl_xor_sync(0xffffffffu, e0, 1);
            e0 += __shfl_xor_sync(0xffffffffu, e0, 2);
            e1 += __shfl_xor_sync(0xffffffffu, e1, 1);
            e1 += __shfl_xor_sync(0xffffffffu, e1, 2);
            if (tig == 0) {
                sEp[nh * 64 + arow]     = e0;
                sEp[nh * 64 + arow + 8] = e1;
            }
        }
        __syncthreads();

        // ---- softmax over K=50 (warp 0) ----
        if (w == 0) {
            float v0 = (lane < K_) ? (sEp[lane] + sEp[64 + lane]) : -1e30f;
            float v1 = (lane + 32 < K_) ? (sEp[lane + 32] + sEp[64 + lane + 32]) : -1e30f;
            float m = fmaxf(v0, v1);
#pragma unroll
            for (int off = 16; off > 0; off >>= 1)
                m = fmaxf(m, __shfl_xor_sync(0xffffffffu, m, off));
            float x0 = (lane < K_) ? __expf(v0 - m) : 0.f;
            float x1 = (lane + 32 < K_) ? __expf(v1 - m) : 0.f;
            float s = x0 + x1;
#pragma unroll
            for (int off = 16; off > 0; off >>= 1)
                s += __shfl_xor_sync(0xffffffffu, s, off);
            float inv = __fdividef(1.f, s);
            if (lane < K_)      sAl[lane]      = x0 * inv;
            if (lane + 32 < K_) sAl[lane + 32] = x1 * inv;
        }
        __syncthreads();

        // ---- weighted sum (fp32 copy of X) ----
        if (tid < 200) {
            float acc = 0.f;
#pragma unroll 5
            for (int k = 0; k < K_; k++) acc += sAl[k] * sXf[k * 200 + tid];
            out[(long long)tile * 200 + tid] = acc;
        }
        __syncthreads();
    }
}

extern "C" void kernel_launch(void* const* d_in, const int* in_sizes, int n_in,
                              void* d_out, int out_size) {
    const unsigned int* ids = nullptr;
    const float *emb = nullptr, *Wht = nullptr, *Wrel = nullptr;
    const float *bht = nullptr, *brel = nullptr;

    for (int i = 0; i < n_in; i++) {
        const int s = in_sizes[i];
        if      (s == B_ * T_ * K_ * 3) ids  = (const unsigned int*)d_in[i];
        else if (s == 500000 * D_)      emb  = (const float*)d_in[i];
        else if (s == D_ * 2 * D_)      Wht  = (const float*)d_in[i];
        else if (s == D_ * D_)          Wrel = (const float*)d_in[i];
        else if (s == D_) {
            if (!bht) bht = (const float*)d_in[i];
            else      brel = (const float*)d_in[i];
        }
    }

    cudaFuncSetAttribute(outer_encoder_mma,
                         cudaFuncAttributeMaxDynamicSharedMemorySize, SMEM_BYTES);
    outer_encoder_mma<<<NBLK, THREADS, SMEM_BYTES>>>(
        ids, emb, Wht, bht, Wrel, brel, (float*)d_out);
}

// round 5
// speedup vs baseline: 7.5600x; 2.2643x over previous
#include <cuda_runtime.h>
#include <cuda_fp16.h>
#include <cstdint>

// Problem constants
static constexpr int B_ = 32, T_ = 200, K_ = 50, D_ = 100;
static constexpr int THREADS = 512;   // 16 warps: warps 0-7 -> tile slot 0, 8-15 -> slot 1
static constexpr int NPAIR = 4;       // tile pairs per CTA
static constexpr int NBLK  = 800;     // 800 x 4 x 2 = 6400 (b,t) tiles

// fp16 weight strides (halfs). B-frag LDS.32 bank pattern verified conflict-free:
// word-stride 108 -> 12*gid+tig distinct mod 32; 60 -> 28*gid+tig distinct.
static constexpr int SWH = 216;   // Wht  [112 x 216]  (cols 200.. zero, rows 100.. zero)
static constexpr int SWR = 120;   // Wrel [112 x 120]  (cols 100.. zero)
// fp32 staging strides (floats). LDS.64 2-phase bank rule: stride mod 32 in {8,24}.
static constexpr int SXF = 216;   // X   [50 x 216] (cols 200..215 zero pad)
static constexpr int SRF = 120;   // REL [50 x 120] (cols 100..119 zero pad)

static constexpr int XF_TILE  = 50 * SXF * 4;   // 43200
static constexpr int RF_TILE  = 50 * SRF * 4;   // 24000

static constexpr int OFF_WHT  = 0;                  // 48384
static constexpr int OFF_WREL = 48384;              // 26880 -> 75264
static constexpr int OFF_XF   = 75264;              // 2*43200 -> 161664
static constexpr int OFF_RELF = 161664;             // 2*24000 -> 209664
static constexpr int OFF_BHT  = 209664;             // 448
static constexpr int OFF_BREL = 210112;             // 448 -> 210560
static constexpr int OFF_EP   = 210560;             // 2*128 floats -> 211584
static constexpr int OFF_AL   = 211584;             // 2*64 floats  -> 212096
static constexpr int OFF_IDS  = 212096;             // 2*152 ints   -> 213312
static constexpr int SMEM_BYTES = 213312;           // 208.3 KB
static constexpr int ZERO_BYTES = OFF_BHT;          // weights + staging (pads must be 0)

__device__ __forceinline__ void mma16816(float& c0, float& c1, float& c2, float& c3,
                                         uint32_t a0, uint32_t a1, uint32_t a2, uint32_t a3,
                                         uint32_t b0, uint32_t b1) {
    asm volatile("mma.sync.aligned.m16n8k16.row.col.f32.f16.f16.f32 "
                 "{%0,%1,%2,%3}, {%4,%5,%6,%7}, {%8,%9}, {%0,%1,%2,%3};"
                 : "+f"(c0), "+f"(c1), "+f"(c2), "+f"(c3)
                 : "r"(a0), "r"(a1), "r"(a2), "r"(a3), "r"(b0), "r"(b1));
}
__device__ __forceinline__ uint32_t f2h2(float a, float b) {
    __half2 h = __floats2half2_rn(a, b);
    return *reinterpret_cast<uint32_t*>(&h);
}
__device__ __forceinline__ float tanh_fast(float x) {
    float e = __expf(2.f * x);
    return __fdividef(e - 1.f, e + 1.f);
}
__device__ __forceinline__ uint32_t smem_u32(const void* p) {
    uint32_t a;
    asm("{ .reg .u64 t; cvta.to.shared.u64 t, %1; cvt.u32.u64 %0, t; }" : "=r"(a) : "l"(p));
    return a;
}
__device__ __forceinline__ void cp_async16(uint32_t dst, const void* src) {
    asm volatile("cp.async.cg.shared.global [%0], [%1], 16;" :: "r"(dst), "l"(src) : "memory");
}
#define CP_COMMIT() asm volatile("cp.async.commit_group;" ::: "memory")
#define CP_WAIT0()  asm volatile("cp.async.wait_group 0;" ::: "memory")
#define BARH(s)     asm volatile("bar.sync %0, 256;" :: "r"((s) + 1) : "memory")

extern __shared__ __align__(16) unsigned char smem_raw[];

__global__ __launch_bounds__(THREADS, 1)
void outer_encoder_mma(const unsigned int* __restrict__ idsw,
                       const float* __restrict__ emb,
                       const float* __restrict__ Wht,
                       const float* __restrict__ bht,
                       const float* __restrict__ Wrel,
                       const float* __restrict__ brel,
                       float* __restrict__ out) {
    unsigned char* sm = smem_raw;
    const uint32_t sb = smem_u32(sm);
    const int tid = threadIdx.x, w = tid >> 5, lane = tid & 31;
    const int s = tid >> 8;               // half-block slot (0/1)
    const int ht = tid & 255;             // thread-in-half
    const int wh = w & 7;                 // warp-in-half
    const int gid = lane >> 2, tig = lane & 3;

    float* sbht = (float*)(sm + OFF_BHT);
    float* sbrl = (float*)(sm + OFF_BREL);
    float* sEp  = (float*)(sm + OFF_EP)  + s * 128;
    float* sAl  = (float*)(sm + OFF_AL)  + s * 64;
    int*   sIds = (int*)  (sm + OFF_IDS) + s * 152;
    float* sXf  = (float*)(sm + OFF_XF   + s * XF_TILE);
    float* sRf  = (float*)(sm + OFF_RELF + s * RF_TILE);

    // ---- zero weights + staging (pad cols/rows must be 0 and stay 0) ----
    for (int i = tid; i < ZERO_BYTES / 16; i += THREADS)
        ((uint4*)sm)[i] = make_uint4(0, 0, 0, 0);
    __syncthreads();

    // ---- weights -> fp16 smem ----
    {
        const float4* g = (const float4*)Wht;              // [100][200] -> 5000 f4
        for (int i = tid; i < 5000; i += THREADS) {
            int d = i / 50, c4 = i % 50;
            float4 v = __ldg(&g[i]);
            uint2 hv; hv.x = f2h2(v.x, v.y); hv.y = f2h2(v.z, v.w);
            *(uint2*)(sm + OFF_WHT + (d * SWH + c4 * 4) * 2) = hv;
        }
        const float4* gr = (const float4*)Wrel;            // [100][100] -> 2500 f4
        for (int i = tid; i < 2500; i += THREADS) {
            int d = i / 25, c4 = i % 25;
            float4 v = __ldg(&gr[i]);
            uint2 hv; hv.x = f2h2(v.x, v.y); hv.y = f2h2(v.z, v.w);
            *(uint2*)(sm + OFF_WREL + (d * SWR + c4 * 4) * 2) = hv;
        }
        if (tid < 112) {
            sbht[tid] = (tid < D_) ? bht[tid]  : 0.f;
            sbrl[tid] = (tid < D_) ? brel[tid] : 0.f;
        }
    }
    const int is64 = ((idsw[1] | idsw[3] | idsw[5] | idsw[7]) == 0) ? 1 : 0;
    __syncthreads();   // weights visible to all; after this the two halves decouple

    const int mt = w & 3, nh = (w >> 2) & 1;
    const int arow  = mt * 16 + gid;
    const int row0  = (arow     < K_) ? arow     : (K_ - 1);   // clamp pad rows
    const int row1  = (arow + 8 < K_) ? arow + 8 : (K_ - 1);
    const __half* pWH = (const __half*)(sm + OFF_WHT);
    const __half* pWR = (const __half*)(sm + OFF_WREL);

    const int tile0 = blockIdx.x * (2 * NPAIR) + s;   // this half's tiles: tile0 + 2*p

    // prologue: ids for first tile
    if (ht < 150) {
        const long long e = (long long)tile0 * 150 + ht;
        sIds[ht] = (int)(is64 ? idsw[2 * e] : idsw[e]);
    }
    BARH(s);

    for (int p = 0; p < NPAIR; p++) {
        const int tile = tile0 + 2 * p;

        // ========== cp.async gather into fp32 staging ==========
        {
            const uint32_t dXb = sb + OFF_XF   + s * XF_TILE + lane * 16;
            const uint32_t dRb = sb + OFF_RELF + s * RF_TILE + lane * 16;
            if (lane < 25) {
                for (int task = wh; task < 100; task += 8) {
                    const int k = task >> 1, h = task & 1;
                    const int id = sIds[k * 3 + (h ? 2 : 0)];
                    cp_async16(dXb + (k * SXF + h * 100) * 4,
                               (const char*)emb + (long long)id * 400 + lane * 16);
                }
                for (int task = wh; task < 50; task += 8) {
                    const int id = sIds[task * 3 + 1];
                    cp_async16(dRb + task * SRF * 4,
                               (const char*)emb + (long long)id * 400 + lane * 16);
                }
            }
            CP_COMMIT();
            CP_WAIT0();
        }
        BARH(s);

        // prefetch next tile's id into a register (latency hidden under MMA)
        int next_id = 0;
        const bool pre = (p + 1 < NPAIR) && (ht < 150);
        if (pre) {
            const long long e = (long long)(tile + 2) * 150 + ht;
            next_id = (int)(is64 ? idsw[2 * e] : idsw[e]);
        }

        // ========== dual GEMM on tensor cores (A converted fp32->fp16 on the fly) ==========
        float acc1[7][4], acc2[7][4];
#pragma unroll
        for (int nt = 0; nt < 7; nt++)
#pragma unroll
            for (int j = 0; j < 4; j++) { acc1[nt][j] = 0.f; acc2[nt][j] = 0.f; }

        {   // GEMM2: D2 = REL[64x112] @ Wrel[112x112]^T  (7 k-steps)
            const float* pA0 = sRf + row0 * SRF;
            const float* pA1 = sRf + row1 * SRF;
#pragma unroll
            for (int ks = 0; ks < 7; ks++) {
                const int k0 = ks * 16 + tig * 2;
                float2 f0 = *(const float2*)(pA0 + k0);
                float2 f1 = *(const float2*)(pA1 + k0);
                float2 f2 = *(const float2*)(pA0 + k0 + 8);
                float2 f3 = *(const float2*)(pA1 + k0 + 8);
                uint32_t a0 = f2h2(f0.x, f0.y), a1 = f2h2(f1.x, f1.y);
                uint32_t a2 = f2h2(f2.x, f2.y), a3 = f2h2(f3.x, f3.y);
#pragma unroll
                for (int nt = 0; nt < 7; nt++) {
                    const int brow = nh * 56 + nt * 8 + gid;
                    uint32_t b0 = *(const uint32_t*)(pWR + brow * SWR + k0);
                    uint32_t b1 = *(const uint32_t*)(pWR + brow * SWR + k0 + 8);
                    mma16816(acc2[nt][0], acc2[nt][1], acc2[nt][2], acc2[nt][3],
                             a0, a1, a2, a3, b0, b1);
                }
            }
        }
        {   // GEMM1: D1 = X[64x208] @ Wht[112x208]^T  (13 k-steps)
            const float* pA0 = sXf + row0 * SXF;
            const float* pA1 = sXf + row1 * SXF;
#pragma unroll
            for (int ks = 0; ks < 13; ks++) {
                const int k0 = ks * 16 + tig * 2;
                float2 f0 = *(const float2*)(pA0 + k0);
                float2 f1 = *(const float2*)(pA1 + k0);
                float2 f2 = *(const float2*)(pA0 + k0 + 8);
                float2 f3 = *(const float2*)(pA1 + k0 + 8);
                uint32_t a0 = f2h2(f0.x, f0.y), a1 = f2h2(f1.x, f1.y);
                uint32_t a2 = f2h2(f2.x, f2.y), a3 = f2h2(f3.x, f3.y);
#pragma unroll
                for (int nt = 0; nt < 7; nt++) {
                    const int brow = nh * 56 + nt * 8 + gid;
                    uint32_t b0 = *(const uint32_t*)(pWH + brow * SWH + k0);
                    uint32_t b1 = *(const uint32_t*)(pWH + brow * SWH + k0 + 8);
                    mma16816(acc1[nt][0], acc1[nt][1], acc1[nt][2], acc1[nt][3],
                             a0, a1, a2, a3, b0, b1);
                }
            }
        }

        // ---- fused epilogue: e partials (pad cols have W=0,b=0 -> contribute 0) ----
        {
            float e0 = 0.f, e1 = 0.f;
#pragma unroll
            for (int nt = 0; nt < 7; nt++) {
                const int c0 = nh * 56 + nt * 8 + tig * 2;
                const float bh0 = sbht[c0], bh1 = sbht[c0 + 1];
                const float br0 = sbrl[c0], br1 = sbrl[c0 + 1];
                e0 += tanh_fast(acc1[nt][0] + bh0) * (acc2[nt][0] + br0)
                    + tanh_fast(acc1[nt][1] + bh1) * (acc2[nt][1] + br1);
                e1 += tanh_fast(acc1[nt][2] + bh0) * (acc2[nt][2] + br0)
                    + tanh_fast(acc1[nt][3] + bh1) * (acc2[nt][3] + br1);
            }
            e0 += __shfl_xor_sync(0xffffffffu, e0, 1);
            e0 += __shfl_xor_sync(0xffffffffu, e0, 2);
            e1 += __shfl_xor_sync(0xffffffffu, e1, 1);
            e1 += __shfl_xor_sync(0xffffffffu, e1, 2);
            if (tig == 0) {
                sEp[nh * 64 + arow]     = e0;
                sEp[nh * 64 + arow + 8] = e1;
            }
        }
        if (pre) sIds[ht] = next_id;       // publish next ids before the barrier
        BARH(s);

        // ---- softmax over K=50 (warp 0 of half) ----
        if (wh == 0) {
            float v0 = (lane < K_) ? (sEp[lane] + sEp[64 + lane]) : -1e30f;
            float v1 = (lane + 32 < K_) ? (sEp[lane + 32] + sEp[64 + lane + 32]) : -1e30f;
            float m = fmaxf(v0, v1);
#pragma unroll
            for (int off = 16; off > 0; off >>= 1)
                m = fmaxf(m, __shfl_xor_sync(0xffffffffu, m, off));
            float x0 = (lane < K_) ? __expf(v0 - m) : 0.f;
            float x1 = (lane + 32 < K_) ? __expf(v1 - m) : 0.f;
            float su = x0 + x1;
#pragma unroll
            for (int off = 16; off > 0; off >>= 1)
                su += __shfl_xor_sync(0xffffffffu, su, off);
            float inv = __fdividef(1.f, su);
            if (lane < K_)      sAl[lane]      = x0 * inv;
            if (lane + 32 < K_) sAl[lane + 32] = x1 * inv;
        }
        BARH(s);

        // ---- weighted sum from fp32 staging ----
        if (ht < 200) {
            float acc = 0.f;
#pragma unroll 5
            for (int k = 0; k < K_; k++) acc += sAl[k] * sXf[k * SXF + ht];
            out[(long long)tile * 200 + ht] = acc;
        }
        BARH(s);   // Xf free for next pair's cp.async
    }
}

extern "C" void kernel_launch(void* const* d_in, const int* in_sizes, int n_in,
                              void* d_out, int out_size) {
    const unsigned int* ids = nullptr;
    const float *emb = nullptr, *Wht = nullptr, *Wrel = nullptr;
    const float *bht = nullptr, *brel = nullptr;

    for (int i = 0; i < n_in; i++) {
        const int sz = in_sizes[i];
        if      (sz == B_ * T_ * K_ * 3) ids  = (const unsigned int*)d_in[i];
        else if (sz == 500000 * D_)      emb  = (const float*)d_in[i];
        else if (sz == D_ * 2 * D_)      Wht  = (const float*)d_in[i];
        else if (sz == D_ * D_)          Wrel = (const float*)d_in[i];
        else if (sz == D_) {
            if (!bht) bht = (const float*)d_in[i];
            else      brel = (const float*)d_in[i];
        }
    }

    cudaFuncSetAttribute(outer_encoder_mma,
                         cudaFuncAttributeMaxDynamicSharedMemorySize, SMEM_BYTES);
    outer_encoder_mma<<<NBLK, THREADS, SMEM_BYTES>>>(
        ids, emb, Wht, bht, Wrel, brel, (float*)d_out);
}

// round 6
// speedup vs baseline: 8.5310x; 1.1284x over previous
#include <cuda_runtime.h>
#include <cuda_fp16.h>
#include <cstdint>

// Problem constants
static constexpr int B_ = 32, T_ = 200, K_ = 50, D_ = 100;
static constexpr int NTILES = B_ * T_;   // 6400
static constexpr int THREADS = 512;      // 16 warps: 2 independent halves of 8

// fp16 weight strides (halfs); fp32 staging strides (floats). Bank patterns verified CF.
static constexpr int SWH = 216;   // Wht  [112 x 216]
static constexpr int SWR = 120;   // Wrel [112 x 120]
static constexpr int SXF = 216;   // X   [50 x 216] fp32 (cols 200..215 zero)
static constexpr int SRF = 120;   // REL [50 x 120] fp32 (cols 100..119 zero)

static constexpr int XF_TILE = 50 * SXF * 4;   // 43200
static constexpr int RF_TILE = 50 * SRF * 4;   // 24000

static constexpr int OFF_WHT  = 0;                  // 48384
static constexpr int OFF_WREL = 48384;              // 26880 -> 75264
static constexpr int OFF_XF   = 75264;              // 2*43200 -> 161664
static constexpr int OFF_RELF = 161664;             // 2*24000 -> 209664
static constexpr int OFF_BHT  = 209664;             // 448
static constexpr int OFF_BREL = 210112;             // 448 -> 210560
static constexpr int OFF_EP   = 210560;             // 2*128 fl -> 211584
static constexpr int OFF_AL   = 211584;             // 2*64 fl  -> 212096
static constexpr int OFF_IDS  = 212096;             // 2 halves * 2 bufs * 152 ints -> 214528
static constexpr int SMEM_BYTES = 214528;
static constexpr int ZERO_BYTES = OFF_BHT;          // weights + staging pads must be 0

__device__ __forceinline__ void mma16816(float& c0, float& c1, float& c2, float& c3,
                                         uint32_t a0, uint32_t a1, uint32_t a2, uint32_t a3,
                                         uint32_t b0, uint32_t b1) {
    asm volatile("mma.sync.aligned.m16n8k16.row.col.f32.f16.f16.f32 "
                 "{%0,%1,%2,%3}, {%4,%5,%6,%7}, {%8,%9}, {%0,%1,%2,%3};"
                 : "+f"(c0), "+f"(c1), "+f"(c2), "+f"(c3)
                 : "r"(a0), "r"(a1), "r"(a2), "r"(a3), "r"(b0), "r"(b1));
}
__device__ __forceinline__ uint32_t f2h2(float a, float b) {
    __half2 h = __floats2half2_rn(a, b);
    return *reinterpret_cast<uint32_t*>(&h);
}
__device__ __forceinline__ float tanh_approx(float x) {
    float y;
    asm("tanh.approx.f32 %0, %1;" : "=f"(y) : "f"(x));
    return y;
}
__device__ __forceinline__ uint32_t smem_u32(const void* p) {
    uint32_t a;
    asm("{ .reg .u64 t; cvta.to.shared.u64 t, %1; cvt.u32.u64 %0, t; }" : "=r"(a) : "l"(p));
    return a;
}
__device__ __forceinline__ void cp_async16(uint32_t dst, const void* src) {
    asm volatile("cp.async.cg.shared.global [%0], [%1], 16;" :: "r"(dst), "l"(src) : "memory");
}
#define CP_COMMIT() asm volatile("cp.async.commit_group;" ::: "memory")
#define CP_WAIT0()  asm volatile("cp.async.wait_group 0;" ::: "memory")
#define BARH(s)     asm volatile("bar.sync %0, 256;" :: "r"((s) + 1) : "memory")

extern __shared__ __align__(16) unsigned char smem_raw[];

__global__ __launch_bounds__(THREADS, 1)
void outer_encoder_mma(const unsigned int* __restrict__ idsw,
                       const float* __restrict__ emb,
                       const float* __restrict__ Wht,
                       const float* __restrict__ bht,
                       const float* __restrict__ Wrel,
                       const float* __restrict__ brel,
                       float* __restrict__ out) {
    unsigned char* sm = smem_raw;
    const uint32_t sb = smem_u32(sm);
    const int tid = threadIdx.x, w = tid >> 5, lane = tid & 31;
    const int s = tid >> 8;               // half-slot (0/1)
    const int ht = tid & 255;             // thread-in-half
    const int wh = w & 7;                 // warp-in-half
    const int gid = lane >> 2, tig = lane & 3;

    float* sbht = (float*)(sm + OFF_BHT);
    float* sbrl = (float*)(sm + OFF_BREL);
    float* sEp  = (float*)(sm + OFF_EP)  + s * 128;
    float* sAl  = (float*)(sm + OFF_AL)  + s * 64;
    int*   sIds = (int*)  (sm + OFF_IDS) + s * 304;   // two buffers of 152
    float* sXf  = (float*)(sm + OFF_XF   + s * XF_TILE);
    float* sRf  = (float*)(sm + OFF_RELF + s * RF_TILE);

    // ---- zero weights + staging (pads must be 0 and stay 0) ----
    for (int i = tid; i < ZERO_BYTES / 16; i += THREADS)
        ((uint4*)sm)[i] = make_uint4(0, 0, 0, 0);
    __syncthreads();

    // ---- weights -> fp16 smem ----
    {
        const float4* g = (const float4*)Wht;              // [100][200] -> 5000 f4
        for (int i = tid; i < 5000; i += THREADS) {
            int d = i / 50, c4 = i % 50;
            float4 v = __ldg(&g[i]);
            uint2 hv; hv.x = f2h2(v.x, v.y); hv.y = f2h2(v.z, v.w);
            *(uint2*)(sm + OFF_WHT + (d * SWH + c4 * 4) * 2) = hv;
        }
        const float4* gr = (const float4*)Wrel;            // [100][100] -> 2500 f4
        for (int i = tid; i < 2500; i += THREADS) {
            int d = i / 25, c4 = i % 25;
            float4 v = __ldg(&gr[i]);
            uint2 hv; hv.x = f2h2(v.x, v.y); hv.y = f2h2(v.z, v.w);
            *(uint2*)(sm + OFF_WREL + (d * SWR + c4 * 4) * 2) = hv;
        }
        if (tid < 112) {
            sbht[tid] = (tid < D_) ? bht[tid]  : 0.f;
            sbrl[tid] = (tid < D_) ? brel[tid] : 0.f;
        }
    }
    const int is64 = ((idsw[1] | idsw[3] | idsw[5] | idsw[7]) == 0) ? 1 : 0;
    __syncthreads();   // after this the two halves decouple

    const int mt = w & 3, nh = (w >> 2) & 1;
    const int arow = mt * 16 + gid;
    const int row0 = (arow     < K_) ? arow     : (K_ - 1);
    const int row1 = (arow + 8 < K_) ? arow + 8 : (K_ - 1);
    const __half* pWH = (const __half*)(sm + OFF_WHT);
    const __half* pWR = (const __half*)(sm + OFF_WREL);
    const uint32_t dXb = sb + OFF_XF   + s * XF_TILE + lane * 16;
    const uint32_t dRb = sb + OFF_RELF + s * RF_TILE + lane * 16;

    const int hs = blockIdx.x * 2 + s;
    const int NH = gridDim.x * 2;

    // ---- prologue: ids + gather for the first tile ----
    if (ht < 150) {
        const long long e = (long long)hs * 150 + ht;
        sIds[ht] = (int)(is64 ? idsw[2 * e] : idsw[e]);
    }
    BARH(s);
    if (lane < 25) {
        for (int task = wh; task < 50; task += 8) {
            const int id = sIds[task * 3 + 1];
            cp_async16(dRb + task * SRF * 4,
                       (const char*)emb + (long long)id * 400 + lane * 16);
        }
        for (int task = wh; task < 100; task += 8) {
            const int k = task >> 1, h = task & 1;
            const int id = sIds[k * 3 + (h ? 2 : 0)];
            cp_async16(dXb + (k * SXF + h * 100) * 4,
                       (const char*)emb + (long long)id * 400 + lane * 16);
        }
    }
    CP_COMMIT();

    int pp = 0;
    for (int tile = hs; tile < NTILES; tile += NH) {
        const bool has_next = (tile + NH) < NTILES;
        int* curIds = sIds + pp * 152;
        int* nxtIds = sIds + (pp ^ 1) * 152;

        CP_WAIT0();
        BARH(s);   // staged data + (prev-iter) id-buffer reads ordered

        // next-tile ids: LDG now, STS after GEMM2 (latency hidden)
        int rid = 0;
        const bool pre = has_next && (ht < 150);
        if (pre) {
            const long long e = (long long)(tile + NH) * 150 + ht;
            rid = (int)(is64 ? idsw[2 * e] : idsw[e]);
        }

        float acc1[7][4], acc2[7][4];
#pragma unroll
        for (int nt = 0; nt < 7; nt++)
#pragma unroll
            for (int j = 0; j < 4; j++) { acc1[nt][j] = 0.f; acc2[nt][j] = 0.f; }

        {   // GEMM2: D2 = REL[64x112] @ Wrel[112x112]^T
            const float* pA0 = sRf + row0 * SRF;
            const float* pA1 = sRf + row1 * SRF;
#pragma unroll
            for (int ks = 0; ks < 7; ks++) {
                const int k0 = ks * 16 + tig * 2;
                float2 f0 = *(const float2*)(pA0 + k0);
                float2 f1 = *(const float2*)(pA1 + k0);
                float2 f2 = *(const float2*)(pA0 + k0 + 8);
                float2 f3 = *(const float2*)(pA1 + k0 + 8);
                uint32_t a0 = f2h2(f0.x, f0.y), a1 = f2h2(f1.x, f1.y);
                uint32_t a2 = f2h2(f2.x, f2.y), a3 = f2h2(f3.x, f3.y);
#pragma unroll
                for (int nt = 0; nt < 7; nt++) {
                    const int brow = nh * 56 + nt * 8 + gid;
                    uint32_t b0 = *(const uint32_t*)(pWR + brow * SWR + k0);
                    uint32_t b1 = *(const uint32_t*)(pWR + brow * SWR + k0 + 8);
                    mma16816(acc2[nt][0], acc2[nt][1], acc2[nt][2], acc2[nt][3],
                             a0, a1, a2, a3, b0, b1);
                }
            }
        }
        if (pre) nxtIds[ht] = rid;
        BARH(s);   // all warps done with sRf; next ids visible

        // overlap: next tile's REL gather streams in under GEMM1 + epilogue
        if (has_next && lane < 25) {
            for (int task = wh; task < 50; task += 8) {
                const int id = nxtIds[task * 3 + 1];
                cp_async16(dRb + task * SRF * 4,
                           (const char*)emb + (long long)id * 400 + lane * 16);
            }
        }

        {   // GEMM1: D1 = X[64x208] @ Wht[112x208]^T
            const float* pA0 = sXf + row0 * SXF;
            const float* pA1 = sXf + row1 * SXF;
#pragma unroll
            for (int ks = 0; ks < 13; ks++) {
                const int k0 = ks * 16 + tig * 2;
                float2 f0 = *(const float2*)(pA0 + k0);
                float2 f1 = *(const float2*)(pA1 + k0);
                float2 f2 = *(const float2*)(pA0 + k0 + 8);
                float2 f3 = *(const float2*)(pA1 + k0 + 8);
                uint32_t a0 = f2h2(f0.x, f0.y), a1 = f2h2(f1.x, f1.y);
                uint32_t a2 = f2h2(f2.x, f2.y), a3 = f2h2(f3.x, f3.y);
#pragma unroll
                for (int nt = 0; nt < 7; nt++) {
                    const int brow = nh * 56 + nt * 8 + gid;
                    uint32_t b0 = *(const uint32_t*)(pWH + brow * SWH + k0);
                    uint32_t b1 = *(const uint32_t*)(pWH + brow * SWH + k0 + 8);
                    mma16816(acc1[nt][0], acc1[nt][1], acc1[nt][2], acc1[nt][3],
                             a0, a1, a2, a3, b0, b1);
                }
            }
        }

        // ---- fused epilogue: e partials (pad cols contribute 0) ----
        {
            float e0 = 0.f, e1 = 0.f;
#pragma unroll
            for (int nt = 0; nt < 7; nt++) {
                const int c0 = nh * 56 + nt * 8 + tig * 2;
                const float bh0 = sbht[c0], bh1 = sbht[c0 + 1];
                const float br0 = sbrl[c0], br1 = sbrl[c0 + 1];
                e0 += tanh_approx(acc1[nt][0] + bh0) * (acc2[nt][0] + br0)
                    + tanh_approx(acc1[nt][1] + bh1) * (acc2[nt][1] + br1);
                e1 += tanh_approx(acc1[nt][2] + bh0) * (acc2[nt][2] + br0)
                    + tanh_approx(acc1[nt][3] + bh1) * (acc2[nt][3] + br1);
            }
            e0 += __shfl_xor_sync(0xffffffffu, e0, 1);
            e0 += __shfl_xor_sync(0xffffffffu, e0, 2);
            e1 += __shfl_xor_sync(0xffffffffu, e1, 1);
            e1 += __shfl_xor_sync(0xffffffffu, e1, 2);
            if (tig == 0) {
                sEp[nh * 64 + arow]     = e0;
                sEp[nh * 64 + arow + 8] = e1;
            }
        }
        BARH(s);   // sXf free; sEp ready

        // overlap: next tile's X gather streams in under softmax + wsum
        if (has_next && lane < 25) {
            for (int task = wh; task < 100; task += 8) {
                const int k = task >> 1, h = task & 1;
                const int id = nxtIds[k * 3 + (h ? 2 : 0)];
                cp_async16(dXb + (k * SXF + h * 100) * 4,
                           (const char*)emb + (long long)id * 400 + lane * 16);
            }
        }
        CP_COMMIT();

        // ---- softmax over K=50 (warp 0 of half) ----
        if (wh == 0) {
            float v0 = (lane < K_) ? (sEp[lane] + sEp[64 + lane]) : -1e30f;
            float v1 = (lane + 32 < K_) ? (sEp[lane + 32] + sEp[64 + lane + 32]) : -1e30f;
            float m = fmaxf(v0, v1);
#pragma unroll
            for (int off = 16; off > 0; off >>= 1)
                m = fmaxf(m, __shfl_xor_sync(0xffffffffu, m, off));
            float x0 = (lane < K_) ? __expf(v0 - m) : 0.f;
            float x1 = (lane + 32 < K_) ? __expf(v1 - m) : 0.f;
            float su = x0 + x1;
#pragma unroll
            for (int off = 16; off > 0; off >>= 1)
                su += __shfl_xor_sync(0xffffffffu, su, off);
            float inv = __fdividef(1.f, su);
            if (lane < K_)      sAl[lane]      = x0 * inv;
            if (lane + 32 < K_) sAl[lane + 32] = x1 * inv;
        }
        BARH(s);

        // ---- weighted sum: re-read emb (L2-hot, coalesced; ids uniform per k) ----
        if (ht < 200) {
            const int part = (ht < 100) ? 0 : 2;
            const int col  = (ht < 100) ? ht : ht - 100;
            float acc = 0.f;
#pragma unroll 5
            for (int k = 0; k < K_; k++) {
                const int id = curIds[k * 3 + part];
                acc += sAl[k] * __ldg(emb + (long long)id * D_ + col);
            }
            out[(long long)tile * 200 + ht] = acc;
        }
        pp ^= 1;
    }
}

extern "C" void kernel_launch(void* const* d_in, const int* in_sizes, int n_in,
                              void* d_out, int out_size) {
    const unsigned int* ids = nullptr;
    const float *emb = nullptr, *Wht = nullptr, *Wrel = nullptr;
    const float *bht = nullptr, *brel = nullptr;

    for (int i = 0; i < n_in; i++) {
        const int sz = in_sizes[i];
        if      (sz == B_ * T_ * K_ * 3) ids  = (const unsigned int*)d_in[i];
        else if (sz == 500000 * D_)      emb  = (const float*)d_in[i];
        else if (sz == D_ * 2 * D_)      Wht  = (const float*)d_in[i];
        else if (sz == D_ * D_)          Wrel = (const float*)d_in[i];
        else if (sz == D_) {
            if (!bht) bht = (const float*)d_in[i];
            else      brel = (const float*)d_in[i];
        }
    }

    int dev = 0;
    cudaGetDevice(&dev);
    int sms = 148;
    cudaDeviceGetAttribute(&sms, cudaDevAttrMultiProcessorCount, dev);
    if (sms <= 0) sms = 148;

    cudaFuncSetAttribute(outer_encoder_mma,
                         cudaFuncAttributeMaxDynamicSharedMemorySize, SMEM_BYTES);
    outer_encoder_mma<<<sms, THREADS, SMEM_BYTES>>>(
        ids, emb, Wht, bht, Wrel, brel, (float*)d_out);
}